// round 5
// baseline (speedup 1.0000x reference)
#include <cuda_runtime.h>

#define N 6000
#define NMS_TH 0.7f
#define MAX_E (1 << 20)
#define NCHUNK 12      // rank chunks of 500
#define GC 12          // cells per axis (cell size 16 over [0,192))
#define NCELL (GC*GC*GC)
#define SUB 8          // lanes per j in k_edges

// ---------------- device scratch ----------------
__device__ int           g_rankpart[NCHUNK * N];
__device__ float4        g_filt[N];              // cx, cy, cz, R2 (rank order)
__device__ float         g_full[N * 8];          // x1,y1,x2,y2,z1,z2,area,score (rank order)
__device__ int           g_cellid[N];
__device__ int           g_cellcnt[NCELL];
__device__ int           g_celloff[NCELL + 1];
__device__ float4        g_cfilt[N];             // filter data in cell-list order
__device__ int           g_crank[N];             // rank index in cell-list order
__device__ int           g_rowcnt[N];
__device__ int           g_rowoff[N + 1];
__device__ int           g_fill[N];
__device__ unsigned int  g_eij[MAX_E];           // (i<<16)|j, i<j
__device__ float         g_ev[MAX_E];
__device__ int           g_csrj[MAX_E];
__device__ float         g_csrv[MAX_E];
__device__ int           g_ecount;

// ---------------- K1: partial rank counts (no atomics) + zero counters ----------------
__global__ void k_rank(const float* __restrict__ scores) {
    __shared__ float ss[500];
    int tx = threadIdx.x;
    int j0 = blockIdx.y * 500;
    for (int jj = tx; jj < 500; jj += 256) ss[jj] = scores[j0 + jj];

    if (blockIdx.x == 0 && blockIdx.y == 0) {
        for (int c = tx; c < NCELL; c += 256) g_cellcnt[c] = 0;
        for (int c = tx; c < N; c += 256) g_rowcnt[c] = 0;
        if (tx == 0) g_ecount = 0;
    }
    __syncthreads();

    int i = blockIdx.x * 256 + tx;
    if (i >= N) return;
    float s = scores[i];
    int c = 0;
#pragma unroll 5
    for (int jj = 0; jj < 500; jj++) {
        float t = ss[jj];
        c += (t > s) || (t == s && (j0 + jj) < i);
    }
    g_rankpart[blockIdx.y * N + i] = c;
}

// ---------------- K2: scatter into sorted order + cell binning ----------------
__global__ void k_scatter(const float* __restrict__ boxes,
                          const float* __restrict__ scores) {
    int gid = blockIdx.x * 256 + threadIdx.x;
    if (gid >= N) return;

    int c = 0;
#pragma unroll
    for (int k = 0; k < NCHUNK; k++) c += g_rankpart[k * N + gid];

    float x1 = boxes[gid * 6 + 0], y1 = boxes[gid * 6 + 1];
    float x2 = boxes[gid * 6 + 2], y2 = boxes[gid * 6 + 3];
    float z1 = boxes[gid * 6 + 4], z2 = boxes[gid * 6 + 5];
    float s = scores[gid];
    g_full[c * 8 + 0] = x1; g_full[c * 8 + 1] = y1;
    g_full[c * 8 + 2] = x2; g_full[c * 8 + 3] = y2;
    g_full[c * 8 + 4] = z1; g_full[c * 8 + 5] = z2;
    g_full[c * 8 + 6] = (x2 - x1) * (y2 - y1) * (z2 - z1);
    g_full[c * 8 + 7] = s;
    float cx = (x2 + x1) * 0.5f, cy = (y2 + y1) * 0.5f, cz = (z1 + z2) * 0.5f;
    float rx = (x2 - x1) * 0.5f, ry = (y2 - y1) * 0.5f, rz = (z2 - z1) * 0.5f;
    float R2 = 0.36f * (rx * rx + ry * ry + rz * rz);
    R2 = R2 * 1.002f + 1e-3f;   // margin vs fp rounding (necessary-condition filter)
    g_filt[c] = make_float4(cx, cy, cz, R2);

    int ix = min(GC - 1, max(0, __float2int_rd(cx * 0.0625f)));
    int iy = min(GC - 1, max(0, __float2int_rd(cy * 0.0625f)));
    int iz = min(GC - 1, max(0, __float2int_rd(cz * 0.0625f)));
    int cid = (iz * GC + iy) * GC + ix;
    g_cellid[c] = cid;
    atomicAdd(&g_cellcnt[cid], 1);
}

// ---------------- K3: cell scan (shuffle-based) + fill cell-ordered arrays ----------------
__global__ void k_cell() {
    __shared__ int wsum[32];
    __shared__ int sfill[NCELL];
    int t = threadIdx.x;
    int a = (2 * t < NCELL) ? g_cellcnt[2 * t] : 0;
    int b = (2 * t + 1 < NCELL) ? g_cellcnt[2 * t + 1] : 0;
    int local = a + b;

    int v = local;
#pragma unroll
    for (int o = 1; o < 32; o <<= 1) {
        int u = __shfl_up_sync(0xFFFFFFFFu, v, o);
        if ((t & 31) >= o) v += u;
    }
    if ((t & 31) == 31) wsum[t >> 5] = v;
    __syncthreads();
    if (t < 32) {
        int w = wsum[t];
#pragma unroll
        for (int o = 1; o < 32; o <<= 1) {
            int u = __shfl_up_sync(0xFFFFFFFFu, w, o);
            if (t >= o) w += u;
        }
        wsum[t] = w;
    }
    __syncthreads();
    int incl = v + ((t >= 32) ? wsum[(t >> 5) - 1] : 0);
    int run = incl - local;
    if (2 * t < NCELL)     { sfill[2 * t] = run;         g_celloff[2 * t] = run; }
    if (2 * t + 1 < NCELL) { sfill[2 * t + 1] = run + a; g_celloff[2 * t + 1] = run + a; }
    if (t == 1023) g_celloff[NCELL] = incl;
    __syncthreads();
    for (int c = t; c < N; c += 1024) {
        int cid = g_cellid[c];
        int pos = atomicAdd(&sfill[cid], 1);
        g_crank[pos] = c;
        g_cfilt[pos] = g_filt[c];
    }
}

// ---------------- K4: edge extraction, 8 lanes per j over spatial grid ----------------
// Coverage proof: DIoU>=0.7 => per-dim |dc| <= 0.6*min(halfwidth) <= 13.2 < 16,
// so the 27-cell neighborhood of j's cell contains every qualifying partner.
__global__ void k_edges() {
    int gt = blockIdx.x * 128 + threadIdx.x;
    int j = gt >> 3;
    int lane = gt & (SUB - 1);
    if (j >= N) return;

    float4 bf = g_filt[j];
    float bx1 = g_full[j * 8 + 0], by1 = g_full[j * 8 + 1];
    float bx2 = g_full[j * 8 + 2], by2 = g_full[j * 8 + 3];
    float bz1 = g_full[j * 8 + 4], bz2 = g_full[j * 8 + 5];
    float barea = g_full[j * 8 + 6];

    int cxi = min(GC - 1, max(0, __float2int_rd(bf.x * 0.0625f)));
    int cyi = min(GC - 1, max(0, __float2int_rd(bf.y * 0.0625f)));
    int czi = min(GC - 1, max(0, __float2int_rd(bf.z * 0.0625f)));
    int zlo = max(0, czi - 1), zhi = min(GC - 1, czi + 1);
    int ylo = max(0, cyi - 1), yhi = min(GC - 1, cyi + 1);
    int xlo = max(0, cxi - 1), xhi = min(GC - 1, cxi + 1);

    for (int zz = zlo; zz <= zhi; zz++)
    for (int yy = ylo; yy <= yhi; yy++) {
        int rowbase = (zz * GC + yy) * GC;
        int s = g_celloff[rowbase + xlo];
        int e = g_celloff[rowbase + xhi + 1];   // x-contiguous cells: one span
        for (int p = s + lane; p < e; p += SUB) {
            float4 f = g_cfilt[p];              // contiguous load
            int i = g_crank[p];
            float dx = bf.x - f.x, dy = bf.y - f.y, dz = bf.z - f.z;
            float d2 = dx * dx + dy * dy + dz * dz;
            if (i < j && d2 <= fminf(f.w, bf.w)) {
                float ax1 = g_full[i * 8 + 0], ay1 = g_full[i * 8 + 1];
                float ax2 = g_full[i * 8 + 2], ay2 = g_full[i * 8 + 3];
                float az1 = g_full[i * 8 + 4], az2 = g_full[i * 8 + 5];
                float iw = fminf(ax2, bx2) - fmaxf(ax1, bx1);
                float ih = fminf(ay2, by2) - fmaxf(ay1, by1);
                float dp = fminf(az2, bz2) - fmaxf(az1, bz1);
                if (iw > 0.0f && ih > 0.0f && dp > 0.0f) {
                    float inter = iw * ih * dp;
                    float uni = g_full[i * 8 + 6] + barea - inter + 1e-7f;
                    float ow = fmaxf(ax2, bx2) - fminf(ax1, bx1);
                    float oh = fmaxf(ay2, by2) - fminf(ay1, by1);
                    float od = fmaxf(az2, bz2) - fminf(az1, bz1);
                    float odiag = ow * ow + oh * oh + od * od + 1e-7f;
                    float v = inter / uni - d2 / odiag;
                    if (v >= NMS_TH) {
                        int e2 = atomicAdd(&g_ecount, 1);
                        if (e2 < MAX_E) {
                            g_eij[e2] = ((unsigned)i << 16) | (unsigned)j;
                            g_ev[e2] = v;
                            atomicAdd(&g_rowcnt[i], 1);
                        }
                    }
                }
            }
        }
    }
}

// ---------------- K5: CSR + fixed-point + merge + outputs (1 block) ----------------
__global__ void k_post(float* __restrict__ out) {
    __shared__ int wsum[32];
    __shared__ unsigned char smask[N];
    __shared__ unsigned char ssup[N];
    int t = threadIdx.x;

    // offsets: per-thread chunk of 6 rows, shuffle-based block scan
    int base = t * 6;
    int cnt6[6];
    int local = 0;
#pragma unroll
    for (int k = 0; k < 6; k++) {
        int idx = base + k;
        cnt6[k] = (idx < N) ? g_rowcnt[idx] : 0;
        local += cnt6[k];
    }
    int v = local;
#pragma unroll
    for (int o = 1; o < 32; o <<= 1) {
        int u = __shfl_up_sync(0xFFFFFFFFu, v, o);
        if ((t & 31) >= o) v += u;
    }
    if ((t & 31) == 31) wsum[t >> 5] = v;
    __syncthreads();
    if (t < 32) {
        int w = wsum[t];
#pragma unroll
        for (int o = 1; o < 32; o <<= 1) {
            int u = __shfl_up_sync(0xFFFFFFFFu, w, o);
            if (t >= o) w += u;
        }
        wsum[t] = w;
    }
    __syncthreads();
    int run = v - local + ((t >= 32) ? wsum[(t >> 5) - 1] : 0);
#pragma unroll
    for (int k = 0; k < 6; k++) {
        int idx = base + k;
        if (idx < N) {
            g_rowoff[idx] = run;
            g_fill[idx] = run;
            run += cnt6[k];
        }
    }
    if (t == 1023) g_rowoff[N] = run;
    __syncthreads();

    int E = g_ecount;
    if (E > MAX_E) E = MAX_E;

    // fill CSR
    for (int e = t; e < E; e += 1024) {
        unsigned p = g_eij[e];
        int i = p >> 16;
        int pos = atomicAdd(&g_fill[i], 1);
        g_csrj[pos] = (int)(p & 0xFFFF);
        g_csrv[pos] = g_ev[e];
    }
    __syncthreads();

    // per-row insertion sort by j (determinism); rows striped by t
    for (int i = t; i < N; i += 1024) {
        int s0 = g_rowoff[i], s1 = g_rowoff[i + 1];
        for (int a = s0 + 1; a < s1; a++) {
            int jv = g_csrj[a]; float vv = g_csrv[a];
            int b = a - 1;
            while (b >= s0 && g_csrj[b] > jv) {
                g_csrj[b + 1] = g_csrj[b];
                g_csrv[b + 1] = g_csrv[b];
                b--;
            }
            g_csrj[b + 1] = jv;
            g_csrv[b + 1] = vv;
        }
    }

    // fixed-point mask iteration
    for (int i = t; i < N; i += 1024) smask[i] = 1;
    __syncthreads();
    for (int it = 0; it < 200; it++) {
        for (int i = t; i < N; i += 1024) ssup[i] = 0;
        __syncthreads();
        for (int e = t; e < E; e += 1024) {
            unsigned p = g_eij[e];
            if (smask[p >> 16]) ssup[p & 0xFFFF] = 1;
        }
        __syncthreads();
        int change = 0;
        for (int i = t; i < N; i += 1024) {
            unsigned char nm = ssup[i] ? 0 : 1;
            if (nm != smask[i]) change = 1;
            smask[i] = nm;
        }
        if (!__syncthreads_or(change)) break;
    }
    __syncthreads();

    // merge + outputs (same row striping as the sort -> same thread, no barrier dep)
    for (int i = t; i < N; i += 1024) {
        float s = g_full[i * 8 + 7];
        float acc[6];
#pragma unroll
        for (int k = 0; k < 6; k++) acc[k] = s * g_full[i * 8 + k];
        float w = s;
        unsigned char m = smask[i];
        if (m) {
            int s0 = g_rowoff[i], s1 = g_rowoff[i + 1];
            for (int e = s0; e < s1; e++) {
                float vv = g_csrv[e];
                if (vv > NMS_TH) {      // strict > for merge weights
                    int jj = g_csrj[e];
                    float wt = vv * g_full[jj * 8 + 7];
                    w += wt;
#pragma unroll
                    for (int k = 0; k < 6; k++) acc[k] += wt * g_full[jj * 8 + k];
                }
            }
        }
#pragma unroll
        for (int k = 0; k < 6; k++) out[i * 6 + k] = acc[k] / w;
        out[N * 6 + i] = m ? 1.0f : 0.0f;
        out[N * 7 + i] = s;
    }
}

// ---------------- launch ----------------
extern "C" void kernel_launch(void* const* d_in, const int* in_sizes, int n_in,
                              void* d_out, int out_size) {
    const float* boxes = (const float*)d_in[0];
    const float* scores = (const float*)d_in[1];
    float* out = (float*)d_out;

    k_rank<<<dim3(24, NCHUNK), 256>>>(scores);
    k_scatter<<<24, 256>>>(boxes, scores);
    k_cell<<<1, 1024>>>();
    k_edges<<<(N * SUB + 127) / 128, 128>>>();
    k_post<<<1, 1024>>>(out);
}

// round 6
// speedup vs baseline: 1.3616x; 1.3616x over previous
#include <cuda_runtime.h>

#define N 6000
#define NMS_TH 0.7f
#define MAX_E (1 << 20)
#define NCHUNK 12      // rank chunks of 500
#define GC 12          // cells per axis (cell size 16 over [0,192))
#define NCELL (GC*GC*GC)

// ---------------- device scratch ----------------
__device__ int           g_rankpart[NCHUNK * N];
__device__ float4        g_filt[N];              // cx, cy, cz, R2 (rank order)
__device__ float         g_full[N * 8];          // x1,y1,x2,y2,z1,z2,area,score (rank order)
__device__ int           g_cellid[N];
__device__ int           g_cellcnt[NCELL];
__device__ int           g_celloff[NCELL + 1];
__device__ float4        g_cfilt[N];             // filter data in cell-list order
__device__ int           g_crank[N];             // rank index in cell-list order
__device__ int           g_rowcnt[N];
__device__ int           g_rowoff[N + 1];
__device__ int           g_fill[N];
__device__ unsigned int  g_eij[MAX_E];           // (i<<16)|j, i<j
__device__ float         g_ev[MAX_E];
__device__ int           g_csrj[MAX_E];
__device__ float         g_csrv[MAX_E];
__device__ int           g_ecount;
__device__ unsigned char g_mask[N];

// ---------------- K1: partial rank counts (no atomics) + zero counters ----------------
__global__ void k_rank(const float* __restrict__ scores) {
    __shared__ float ss[500];
    int tx = threadIdx.x;
    int j0 = blockIdx.y * 500;
    for (int jj = tx; jj < 500; jj += 256) ss[jj] = scores[j0 + jj];

    if (blockIdx.x == 0 && blockIdx.y == 0) {
        for (int c = tx; c < NCELL; c += 256) g_cellcnt[c] = 0;
        for (int c = tx; c < N; c += 256) g_rowcnt[c] = 0;
        if (tx == 0) g_ecount = 0;
    }
    __syncthreads();

    int i = blockIdx.x * 256 + tx;
    if (i >= N) return;
    float s = scores[i];
    int c = 0;
#pragma unroll 5
    for (int jj = 0; jj < 500; jj++) {
        float t = ss[jj];
        c += (t > s) || (t == s && (j0 + jj) < i);
    }
    g_rankpart[blockIdx.y * N + i] = c;
}

// ---------------- K2: scatter into sorted order + cell binning ----------------
__global__ void k_scatter(const float* __restrict__ boxes,
                          const float* __restrict__ scores) {
    int gid = blockIdx.x * 256 + threadIdx.x;
    if (gid >= N) return;

    int c = 0;
#pragma unroll
    for (int k = 0; k < NCHUNK; k++) c += g_rankpart[k * N + gid];

    float x1 = boxes[gid * 6 + 0], y1 = boxes[gid * 6 + 1];
    float x2 = boxes[gid * 6 + 2], y2 = boxes[gid * 6 + 3];
    float z1 = boxes[gid * 6 + 4], z2 = boxes[gid * 6 + 5];
    float s = scores[gid];
    g_full[c * 8 + 0] = x1; g_full[c * 8 + 1] = y1;
    g_full[c * 8 + 2] = x2; g_full[c * 8 + 3] = y2;
    g_full[c * 8 + 4] = z1; g_full[c * 8 + 5] = z2;
    g_full[c * 8 + 6] = (x2 - x1) * (y2 - y1) * (z2 - z1);
    g_full[c * 8 + 7] = s;
    float cx = (x2 + x1) * 0.5f, cy = (y2 + y1) * 0.5f, cz = (z1 + z2) * 0.5f;
    float rx = (x2 - x1) * 0.5f, ry = (y2 - y1) * 0.5f, rz = (z2 - z1) * 0.5f;
    float R2 = 0.36f * (rx * rx + ry * ry + rz * rz);
    R2 = R2 * 1.002f + 1e-3f;   // margin vs fp rounding (necessary-condition filter)
    g_filt[c] = make_float4(cx, cy, cz, R2);

    int ix = min(GC - 1, max(0, __float2int_rd(cx * 0.0625f)));
    int iy = min(GC - 1, max(0, __float2int_rd(cy * 0.0625f)));
    int iz = min(GC - 1, max(0, __float2int_rd(cz * 0.0625f)));
    int cid = (iz * GC + iy) * GC + ix;
    g_cellid[c] = cid;
    atomicAdd(&g_cellcnt[cid], 1);
}

// ---------------- K3: cell scan (shuffle-based) + fill cell-ordered arrays ----------------
__global__ void k_cell() {
    __shared__ int wsum[32];
    __shared__ int sfill[NCELL];
    int t = threadIdx.x;
    int a = (2 * t < NCELL) ? g_cellcnt[2 * t] : 0;
    int b = (2 * t + 1 < NCELL) ? g_cellcnt[2 * t + 1] : 0;
    int local = a + b;

    int v = local;
#pragma unroll
    for (int o = 1; o < 32; o <<= 1) {
        int u = __shfl_up_sync(0xFFFFFFFFu, v, o);
        if ((t & 31) >= o) v += u;
    }
    if ((t & 31) == 31) wsum[t >> 5] = v;
    __syncthreads();
    if (t < 32) {
        int w = wsum[t];
#pragma unroll
        for (int o = 1; o < 32; o <<= 1) {
            int u = __shfl_up_sync(0xFFFFFFFFu, w, o);
            if (t >= o) w += u;
        }
        wsum[t] = w;
    }
    __syncthreads();
    int incl = v + ((t >= 32) ? wsum[(t >> 5) - 1] : 0);
    int run = incl - local;
    if (2 * t < NCELL)     { sfill[2 * t] = run;         g_celloff[2 * t] = run; }
    if (2 * t + 1 < NCELL) { sfill[2 * t + 1] = run + a; g_celloff[2 * t + 1] = run + a; }
    if (t == 1023) g_celloff[NCELL] = incl;
    __syncthreads();
    for (int c = t; c < N; c += 1024) {
        int cid = g_cellid[c];
        int pos = atomicAdd(&sfill[cid], 1);
        g_crank[pos] = c;
        g_cfilt[pos] = g_filt[c];
    }
}

// ---------------- K4: edge extraction, one warp per (j, z-row) ----------------
// Coverage proof: DIoU>=0.7 => per-dim |dc| <= 0.6*min(halfwidth) <= 13.2 < 16,
// so the 27-cell neighborhood of j's cell contains every qualifying partner.
// Work split: 3 warps per j (dz = -1, 0, +1), each scans its z-row's 3 y-spans.
__global__ void k_edges() {
    int gt = blockIdx.x * 256 + threadIdx.x;
    int task = gt >> 5;
    int lane = gt & 31;
    if (task >= N * 3) return;
    int j = task / 3;
    int dz = task - j * 3 - 1;     // -1, 0, +1

    float4 bf = g_filt[j];
    int czi = min(GC - 1, max(0, __float2int_rd(bf.z * 0.0625f)));
    int zz = czi + dz;
    if (zz < 0 || zz >= GC) return;

    float bx1 = g_full[j * 8 + 0], by1 = g_full[j * 8 + 1];
    float bx2 = g_full[j * 8 + 2], by2 = g_full[j * 8 + 3];
    float bz1 = g_full[j * 8 + 4], bz2 = g_full[j * 8 + 5];
    float barea = g_full[j * 8 + 6];

    int cxi = min(GC - 1, max(0, __float2int_rd(bf.x * 0.0625f)));
    int cyi = min(GC - 1, max(0, __float2int_rd(bf.y * 0.0625f)));
    int ylo = max(0, cyi - 1), yhi = min(GC - 1, cyi + 1);
    int xlo = max(0, cxi - 1), xhi = min(GC - 1, cxi + 1);

    for (int yy = ylo; yy <= yhi; yy++) {
        int rowbase = (zz * GC + yy) * GC;
        int s = g_celloff[rowbase + xlo];
        int e = g_celloff[rowbase + xhi + 1];   // x-contiguous cells: one span
        for (int p = s + lane; p < e; p += 32) {
            float4 f = g_cfilt[p];              // contiguous per-warp load
            int i = g_crank[p];
            float dx = bf.x - f.x, dy = bf.y - f.y, dz2 = bf.z - f.z;
            float d2 = dx * dx + dy * dy + dz2 * dz2;
            if (i < j && d2 <= fminf(f.w, bf.w)) {
                float ax1 = g_full[i * 8 + 0], ay1 = g_full[i * 8 + 1];
                float ax2 = g_full[i * 8 + 2], ay2 = g_full[i * 8 + 3];
                float az1 = g_full[i * 8 + 4], az2 = g_full[i * 8 + 5];
                float iw = fminf(ax2, bx2) - fmaxf(ax1, bx1);
                float ih = fminf(ay2, by2) - fmaxf(ay1, by1);
                float dp = fminf(az2, bz2) - fmaxf(az1, bz1);
                if (iw > 0.0f && ih > 0.0f && dp > 0.0f) {
                    float inter = iw * ih * dp;
                    float uni = g_full[i * 8 + 6] + barea - inter + 1e-7f;
                    float ow = fmaxf(ax2, bx2) - fminf(ax1, bx1);
                    float oh = fmaxf(ay2, by2) - fminf(ay1, by1);
                    float od = fmaxf(az2, bz2) - fminf(az1, bz1);
                    float odiag = ow * ow + oh * oh + od * od + 1e-7f;
                    float v = inter / uni - d2 / odiag;
                    if (v >= NMS_TH) {
                        int e2 = atomicAdd(&g_ecount, 1);
                        if (e2 < MAX_E) {
                            g_eij[e2] = ((unsigned)i << 16) | (unsigned)j;
                            g_ev[e2] = v;
                            atomicAdd(&g_rowcnt[i], 1);
                        }
                    }
                }
            }
        }
    }
}

// ---------------- K5: CSR build + sort + fixed-point iteration (1 block) ----------------
__global__ void k_post() {
    __shared__ int wsum[32];
    __shared__ unsigned char smask[N];
    __shared__ unsigned char ssup[N];
    int t = threadIdx.x;

    // offsets: per-thread chunk of 6 rows, shuffle-based block scan
    int base = t * 6;
    int cnt6[6];
    int local = 0;
#pragma unroll
    for (int k = 0; k < 6; k++) {
        int idx = base + k;
        cnt6[k] = (idx < N) ? g_rowcnt[idx] : 0;
        local += cnt6[k];
    }
    int v = local;
#pragma unroll
    for (int o = 1; o < 32; o <<= 1) {
        int u = __shfl_up_sync(0xFFFFFFFFu, v, o);
        if ((t & 31) >= o) v += u;
    }
    if ((t & 31) == 31) wsum[t >> 5] = v;
    __syncthreads();
    if (t < 32) {
        int w = wsum[t];
#pragma unroll
        for (int o = 1; o < 32; o <<= 1) {
            int u = __shfl_up_sync(0xFFFFFFFFu, w, o);
            if (t >= o) w += u;
        }
        wsum[t] = w;
    }
    __syncthreads();
    int run = v - local + ((t >= 32) ? wsum[(t >> 5) - 1] : 0);
#pragma unroll
    for (int k = 0; k < 6; k++) {
        int idx = base + k;
        if (idx < N) {
            g_rowoff[idx] = run;
            g_fill[idx] = run;
            run += cnt6[k];
        }
    }
    if (t == 1023) g_rowoff[N] = run;
    __syncthreads();

    int E = g_ecount;
    if (E > MAX_E) E = MAX_E;

    // fill CSR
    for (int e = t; e < E; e += 1024) {
        unsigned p = g_eij[e];
        int i = p >> 16;
        int pos = atomicAdd(&g_fill[i], 1);
        g_csrj[pos] = (int)(p & 0xFFFF);
        g_csrv[pos] = g_ev[e];
    }
    __syncthreads();

    // per-row insertion sort by j (determinism)
    for (int i = t; i < N; i += 1024) {
        int s0 = g_rowoff[i], s1 = g_rowoff[i + 1];
        for (int a = s0 + 1; a < s1; a++) {
            int jv = g_csrj[a]; float vv = g_csrv[a];
            int b = a - 1;
            while (b >= s0 && g_csrj[b] > jv) {
                g_csrj[b + 1] = g_csrj[b];
                g_csrv[b + 1] = g_csrv[b];
                b--;
            }
            g_csrj[b + 1] = jv;
            g_csrv[b + 1] = vv;
        }
    }

    // fixed-point mask iteration
    for (int i = t; i < N; i += 1024) smask[i] = 1;
    __syncthreads();
    for (int it = 0; it < 200; it++) {
        for (int i = t; i < N; i += 1024) ssup[i] = 0;
        __syncthreads();
        for (int e = t; e < E; e += 1024) {
            unsigned p = g_eij[e];
            if (smask[p >> 16]) ssup[p & 0xFFFF] = 1;
        }
        __syncthreads();
        int change = 0;
        for (int i = t; i < N; i += 1024) {
            unsigned char nm = ssup[i] ? 0 : 1;
            if (nm != smask[i]) change = 1;
            smask[i] = nm;
        }
        if (!__syncthreads_or(change)) break;
    }
    for (int i = t; i < N; i += 1024) g_mask[i] = smask[i];
}

// ---------------- K6: merge from CSR + write outputs (multi-block) ----------------
__global__ void k_final(float* __restrict__ out) {
    int i = blockIdx.x * 256 + threadIdx.x;
    if (i >= N) return;
    float s = g_full[i * 8 + 7];
    float acc[6];
#pragma unroll
    for (int k = 0; k < 6; k++) acc[k] = s * g_full[i * 8 + k];
    float w = s;
    unsigned char m = g_mask[i];
    if (m) {
        int s0 = g_rowoff[i], s1 = g_rowoff[i + 1];
        for (int e = s0; e < s1; e++) {
            float v = g_csrv[e];
            if (v > NMS_TH) {           // strict > for merge weights
                int j = g_csrj[e];
                float wt = v * g_full[j * 8 + 7];
                w += wt;
#pragma unroll
                for (int k = 0; k < 6; k++) acc[k] += wt * g_full[j * 8 + k];
            }
        }
    }
#pragma unroll
    for (int k = 0; k < 6; k++) out[i * 6 + k] = acc[k] / w;
    out[N * 6 + i] = m ? 1.0f : 0.0f;
    out[N * 7 + i] = s;
}

// ---------------- launch ----------------
extern "C" void kernel_launch(void* const* d_in, const int* in_sizes, int n_in,
                              void* d_out, int out_size) {
    const float* boxes = (const float*)d_in[0];
    const float* scores = (const float*)d_in[1];
    float* out = (float*)d_out;

    k_rank<<<dim3(24, NCHUNK), 256>>>(scores);
    k_scatter<<<24, 256>>>(boxes, scores);
    k_cell<<<1, 1024>>>();
    k_edges<<<(N * 3 * 32 + 255) / 256, 256>>>();
    k_post<<<1, 1024>>>();
    k_final<<<24, 256>>>(out);
}